// round 16
// baseline (speedup 1.0000x reference)
#include <cuda_runtime.h>
#include <math.h>

#define N 2048
#define K 8
#define FN 16
#define O 32

#define TJ 128                 // j-columns per block
#define TI 64                  // i-rows per block
#define NJB (N / TJ)           // 16
#define NBLK ((N / TJ) * (N / TI))  // 512

// Scratch (allocation-free): __device__ globals (zero-initialized at load)
__device__ float g_rinv[N];
__device__ float g_agg[N * K];
__device__ float g_col[N];
__device__ unsigned int g_jbdone[NJB];   // monotonic across graph replays

// Kernel 1: barrier-free warp-per-row row sums + scratch zero (measured
// 6.9-7.2us, best of three shapes; remaining cost is a per-kernel floor).
__global__ void __launch_bounds__(128) k_rowsum(const float* __restrict__ adj) {
    int warp_g = (blockIdx.x * blockDim.x + threadIdx.x) >> 5;  // 0..2047
    int lane   = threadIdx.x & 31;
    int row    = warp_g;

    const float4* r = (const float4*)(adj + (size_t)row * N);  // 512 float4s

    float s = 0.0f;
    #pragma unroll
    for (int u = 0; u < 16; ++u) {
        float4 v = __ldg(r + lane + 32 * u);
        s += (v.x + v.y) + (v.z + v.w);
    }

    #pragma unroll
    for (int off = 16; off; off >>= 1) s += __shfl_xor_sync(0xFFFFFFFFu, s, off);

    // Zero this row's accumulator scratch (lanes 0..7 -> agg, lane 8 -> col)
    if (lane < K) g_agg[row * K + lane] = 0.0f;
    else if (lane == K) g_col[row] = 0.0f;

    if (lane == 0) {
        float inv = 1.0f / s;
        if (!isfinite(inv)) inv = 0.0f;
        g_rinv[row] = inv;
    }
}

// Kernel 2: accumulation (measured-best u8 + __ldcs body, verbatim) with the
// epilogue FUSED via a per-jb monotonic completion counter. No thread ever
// waits: each block increments its jb counter once; the 32nd arrival (per
// run) computes that j-column's 128x32 outputs. Deadlock-free by
// construction (no spinning), deterministic across graph replays (exactly
// 32 arrivals per jb per execution; (old & 31)==31 fires exactly once).
// Accum table (us): u8+ldcs 22.0/24.6 | u16+ldcs 31.3 | u4+ldcs 34.6 |
// u4 plain 39.7  -> u8+ldcs is the sweet spot, do not touch.
__global__ void __launch_bounds__(256) k_accum_epi(
    const float* __restrict__ E,
    const float* __restrict__ adj,
    const float* __restrict__ nf,
    const float* __restrict__ W,
    float* __restrict__ out)
{
    const int nJBc = NJB;                   // 16
    int jb = blockIdx.x % nJBc;
    int ib = blockIdx.x / nJBc;
    int j0 = jb * TJ;
    int i0 = ib * TI;

    int tid = threadIdx.x;                  // 0..255
    int e0  = tid * 4;                      // element in [0, TJ*K)
    int jl  = e0 >> 3;                      // local j (= tid/2)
    int k0  = e0 & 7;                       // 0 or 4

    __shared__ float s_rinv[TI];
    __shared__ float sW[(K + FN) * O];
    __shared__ int s_fin;

    if (tid < TI) s_rinv[tid] = g_rinv[i0 + tid];
    __syncthreads();

    float4 acc = make_float4(0.f, 0.f, 0.f, 0.f);
    float colp = 0.0f;

    const float* Ebase = E + ((size_t)i0 * N + j0) * K + e0;
    const float* Abase = adj + (size_t)i0 * N + j0 + jl;

    #pragma unroll 8
    for (int ii = 0; ii < TI; ++ii) {
        float s = s_rinv[ii] * __ldg(Abase + (size_t)ii * N);
        float4 ev = __ldcs((const float4*)(Ebase + (size_t)ii * N * K));
        acc.x = fmaf(s, ev.x, acc.x);
        acc.y = fmaf(s, ev.y, acc.y);
        acc.z = fmaf(s, ev.z, acc.z);
        acc.w = fmaf(s, ev.w, acc.w);
        if (k0 == 0) colp += s;
    }

    int j = j0 + jl;
    float* ag = &g_agg[j * K + k0];
    atomicAdd(ag + 0, acc.x);
    atomicAdd(ag + 1, acc.y);
    atomicAdd(ag + 2, acc.z);
    atomicAdd(ag + 3, acc.w);
    if (k0 == 0) atomicAdd(&g_col[j], colp);

    // ---- epilogue gate: last accum block of this j-column does the GEMM ----
    __threadfence();
    __syncthreads();
    if (tid == 0) {
        unsigned int old = atomicAdd(&g_jbdone[jb], 1u);
        s_fin = ((old & 31u) == 31u) ? 1 : 0;   // 32 ib-blocks per jb per run
    }
    __syncthreads();
    if (!s_fin) return;

    // Stage W (24x32 = 768 floats) in smem
    for (int idx = tid; idx < (K + FN) * O; idx += 256) sW[idx] = __ldg(&W[idx]);
    __syncthreads();

    {
        int jr = tid >> 1;                // 0..127 : local j
        int ob = (tid & 1) * 16;          // output col base
        int jj = j0 + jr;

        float col = __ldcg(&g_col[jj]);
        float aggv[K];
        #pragma unroll
        for (int k = 0; k < K; ++k) aggv[k] = __ldcg(&g_agg[jj * K + k]);
        float nfv[FN];
        #pragma unroll
        for (int f = 0; f < FN; ++f) nfv[f] = __ldg(&nf[jj * FN + f]);

        #pragma unroll
        for (int oo = 0; oo < 16; ++oo) {
            int o = ob + oo;
            float r = 0.0f, nn = 0.0f;
            #pragma unroll
            for (int k = 0; k < K; ++k)  r  = fmaf(aggv[k], sW[k * O + o], r);
            #pragma unroll
            for (int f = 0; f < FN; ++f) nn = fmaf(nfv[f], sW[(K + f) * O + o], nn);
            out[jj * O + o] = r + col * nn;
        }
    }
}

extern "C" void kernel_launch(void* const* d_in, const int* in_sizes, int n_in,
                              void* d_out, int out_size) {
    const float* node_features = (const float*)d_in[0];   // (N, FN)
    const float* edge_feat     = (const float*)d_in[1];   // (N, N, K)
    const float* adj           = (const float*)d_in[2];   // (N, N)
    const float* weight        = (const float*)d_in[3];   // (K+FN, O)
    float* out = (float*)d_out;                           // (N, O)

    // 1) row sums + scratch zero: warp per row, 2048 warps
    k_rowsum<<<N / 4, 128>>>(adj);
    // 2) accumulation + fused epilogue: 512 blocks
    k_accum_epi<<<NBLK, 256>>>(edge_feat, adj, node_features, weight, out);
}